// round 2
// baseline (speedup 1.0000x reference)
#include <cuda_runtime.h>
#include <math.h>

// ---------------- problem constants ----------------
#define T_LEN 131072
#define NB 16            // batch
#define NCHA 2           // audio channels
#define NSEQ (NB*NCHA)   // 32 filter sequences
#define NBAND 3
#define NBS (NBAND*NB)   // 48 band-smoother sequences
#define SRATE 44100.0f

// biquad blocked-scan config
#define BQ_NT 1024
#define BQ_C (T_LEN/BQ_NT)    // 128 samples per thread
#define BQ_LEV 10             // log2(BQ_NT)

// smoothing chunk config
#define SM_CHUNK 4096
#define SM_NCH (T_LEN/SM_CHUNK)   // 32 chunks
#define SM_WARM 24576             // warmup samples (contraction e^-12.3)

// ---------------- scratch (static device arrays; no allocation) ----------------
__device__ float g_xd [NSEQ*T_LEN];   // distorted input
__device__ float g_t1 [NSEQ*T_LEN];   // low biquad pass 1
__device__ float g_t2 [NSEQ*T_LEN];   // high biquad pass 1
__device__ float g_low[NSEQ*T_LEN];
__device__ float g_high[NSEQ*T_LEN];
__device__ float g_gin[NBS*T_LEN];    // instantaneous band gains
__device__ float g_gsm[NBS*T_LEN];    // smoothed band gains
__device__ float g_xm [NSEQ*T_LEN];   // multiband-mixed signal
__device__ float g_det[NB*T_LEN];     // limiter detector
__device__ float g_lg [NB*T_LEN];     // limiter gain

struct BQ  { float na1, na2, b0, k1, k2; };     // DF2T: z1'=na1*z1+z2+k1*x ; z2'=na2*z1+k2*x ; y=b0*x+z1
struct BSM { float at, rt, ct, sc, et, se; int useMin; };
struct LSM { float at, rt, lt; int useMin; };

__device__ BQ  d_bq[2*NB];     // [0..15] low, [16..31] high
__device__ BSM d_bsm[NBS];     // band-major: seq = band*16 + b
__device__ LSM d_lsm[NB];
__device__ float d_w[NB], d_gd[NB], d_mb[NB];

// ---------------- setup ----------------
__global__ void k_setup(const float* __restrict__ drive, const float* __restrict__ dmix,
                        const float* __restrict__ locut, const float* __restrict__ hicut,
                        const float* __restrict__ mbmix,
                        const float* __restrict__ ct, const float* __restrict__ cr,
                        const float* __restrict__ et, const float* __restrict__ er,
                        const float* __restrict__ atms, const float* __restrict__ rtms,
                        const float* __restrict__ lth, const float* __restrict__ lat,
                        const float* __restrict__ lrt)
{
    int i = threadIdx.x;
    if (i < NB) {
        d_w[i]  = dmix[i];
        d_gd[i] = exp2f(drive[i] * 0.16609640474436813f);   // 10^(db/20)
        d_mb[i] = mbmix[i];
        for (int f = 0; f < 2; ++f) {
            double cut = (f == 0) ? (double)locut[i] : (double)hicut[i];
            double w0 = 2.0 * 3.14159265358979323846 * cut / 44100.0;
            double al = sin(w0) * 0.70710678118654752;
            double c  = cos(w0);
            double b0, b1, b2;
            if (f == 0) { b0 = (1.0 - c) * 0.5; b1 = 1.0 - c;    b2 = (1.0 - c) * 0.5; }
            else        { b0 = (1.0 + c) * 0.5; b1 = -(1.0 + c); b2 = (1.0 + c) * 0.5; }
            double a0 = 1.0 + al;
            b0 /= a0; b1 /= a0; b2 /= a0;
            double a1 = -2.0 * c / a0, a2 = (1.0 - al) / a0;
            BQ q;
            q.na1 = (float)(-a1); q.na2 = (float)(-a2); q.b0 = (float)b0;
            q.k1  = (float)(b1 - a1 * b0);
            q.k2  = (float)(b2 - a2 * b0);
            d_bq[f*NB + i] = q;
        }
        float at = 1.f - expf(-2200.f / (lat[i] * SRATE));
        float rt = 1.f - expf(-2200.f / (lrt[i] * SRATE));
        LSM l; l.at = at; l.rt = rt;
        l.lt = exp2f(lth[i] * 0.16609640474436813f);
        l.useMin = (at < rt);   // attack_on_rise=True
        d_lsm[i] = l;
    }
    if (i < NBS) {
        int band = i / NB, b = i % NB;
        int idx = b*3 + band;
        float at = 1.f - expf(-2200.f / (atms[idx] * SRATE));
        float rt = 1.f - expf(-2200.f / (rtms[idx] * SRATE));
        BSM s;
        s.at = at; s.rt = rt; s.useMin = (at >= rt);   // attack_on_rise=False
        s.ct = ct[idx]; s.sc = 1.f - 1.f / cr[idx];
        s.et = et[idx]; s.se = 1.f - 1.f / er[idx];
        d_bsm[i] = s;
    }
}

// ---------------- distortion ----------------
__global__ void k_dist(const float* __restrict__ x)
{
    int idx = blockIdx.x * blockDim.x + threadIdx.x;
    const int n4 = NSEQ * T_LEN / 4;
    if (idx >= n4) return;
    int b = idx >> 16;                  // (NCHA*T_LEN/4) = 65536 float4 per batch
    float w = d_w[b], gd = d_gd[b], ow = 1.f - w;
    float4 v = __ldg(((const float4*)x) + idx);
    v.x = fmaf(w, tanhf(v.x * gd), ow * v.x);
    v.y = fmaf(w, tanhf(v.y * gd), ow * v.y);
    v.z = fmaf(w, tanhf(v.z * gd), ow * v.z);
    v.w = fmaf(w, tanhf(v.w * gd), ow * v.w);
    ((float4*)g_xd)[idx] = v;
}

// ---------------- biquad (blocked state-space scan, exact) ----------------
__device__ __forceinline__ void bqstep(float x, float& z1, float& z2, const BQ& c)
{
    float t  = fmaf(c.k1, x, z2);
    float n2 = fmaf(c.na2, z1, c.k2 * x);
    z1 = fmaf(c.na1, z1, t);
    z2 = n2;
}
__device__ __forceinline__ float bqstep_y(float x, float& z1, float& z2, const BQ& c)
{
    float y  = fmaf(c.b0, x, z1);
    float t  = fmaf(c.k1, x, z2);
    float n2 = fmaf(c.na2, z1, c.k2 * x);
    z1 = fmaf(c.na1, z1, t);
    z2 = n2;
    return y;
}

__global__ void k_biquad(int pass)
{
    __shared__ float2 sF[BQ_NT];
    __shared__ float  sP[BQ_LEV][4];
    int blk = blockIdx.x;
    int f = blk >> 5;          // 0 = low chain, 1 = high chain
    int s = blk & 31;          // sequence (b*2 + ch)
    int b = s >> 1;
    const float* in; float* out;
    if (pass == 0) { in = g_xd;              out = f ? g_t2  : g_t1; }
    else           { in = f ? g_t2 : g_t1;   out = f ? g_high : g_low; }
    BQ cf = d_bq[f*NB + b];
    int tid = threadIdx.x;

    if (tid == 0) {
        // A = [[na1, 1],[na2, 0]]; compute A^128 then its squarings, in double
        double m00 = (double)cf.na1, m01 = 1.0, m10 = (double)cf.na2, m11 = 0.0;
        for (int k = 0; k < 7; ++k) {
            double t00 = m00*m00 + m01*m10, t01 = m00*m01 + m01*m11;
            double t10 = m10*m00 + m11*m10, t11 = m10*m01 + m11*m11;
            m00 = t00; m01 = t01; m10 = t10; m11 = t11;
        }
        for (int lv = 0; lv < BQ_LEV; ++lv) {
            sP[lv][0] = (float)m00; sP[lv][1] = (float)m01;
            sP[lv][2] = (float)m10; sP[lv][3] = (float)m11;
            double t00 = m00*m00 + m01*m10, t01 = m00*m01 + m01*m11;
            double t10 = m10*m00 + m11*m10, t11 = m10*m01 + m11*m11;
            m00 = t00; m01 = t01; m10 = t10; m11 = t11;
        }
    }

    const float4* in4 = (const float4*)(in + (size_t)s * T_LEN + (size_t)tid * BQ_C);

    // phase A: zero-state run, keep only final state
    float z1 = 0.f, z2 = 0.f;
#pragma unroll 8
    for (int i = 0; i < BQ_C/4; ++i) {
        float4 v = __ldg(in4 + i);
        bqstep(v.x, z1, z2, cf);
        bqstep(v.y, z1, z2, cf);
        bqstep(v.z, z1, z2, cf);
        bqstep(v.w, z1, z2, cf);
    }
    __syncthreads();   // sP visible + sF safe

    // Kogge-Stone scan: F_j = sum_{i<=j} (A^C)^(j-i) s_i
    float2 my = make_float2(z1, z2);
#pragma unroll
    for (int lv = 0; lv < BQ_LEV; ++lv) {
        sF[tid] = my;
        __syncthreads();
        int d = 1 << lv;
        if (tid >= d) {
            float2 o = sF[tid - d];
            float p00 = sP[lv][0], p01 = sP[lv][1], p10 = sP[lv][2], p11 = sP[lv][3];
            my.x += p00 * o.x + p01 * o.y;
            my.y += p10 * o.x + p11 * o.y;
        }
        __syncthreads();
    }
    sF[tid] = my;
    __syncthreads();
    float2 e = (tid > 0) ? sF[tid - 1] : make_float2(0.f, 0.f);

    // phase B: re-run with correct incoming state, emit outputs
    z1 = e.x; z2 = e.y;
    float4* out4 = (float4*)(out + (size_t)s * T_LEN + (size_t)tid * BQ_C);
#pragma unroll 8
    for (int i = 0; i < BQ_C/4; ++i) {
        float4 v = __ldg(in4 + i);
        float4 r;
        r.x = bqstep_y(v.x, z1, z2, cf);
        r.y = bqstep_y(v.y, z1, z2, cf);
        r.z = bqstep_y(v.z, z1, z2, cf);
        r.w = bqstep_y(v.w, z1, z2, cf);
        out4[i] = r;
    }
}

// ---------------- instantaneous band gain ----------------
__device__ __forceinline__ float comp_gain(float det, const BSM& p)
{
    float xdb = 6.0205999132796239f * log2f(fmaxf(det, 1e-7f));   // 20*log10
    float gdb = fminf(fminf(p.sc * (p.ct - xdb), p.se * (p.et - xdb)), 0.f);
    return exp2f(gdb * 0.16609640474436813f);                      // 10^(gdb/20)
}

__global__ void k_bandgain()
{
    int idx = blockIdx.x * blockDim.x + threadIdx.x;
    const int per = T_LEN / 4;
    if (idx >= NB * per) return;
    int b = idx / per, t4 = idx - b * per;
    size_t o0 = (size_t)b * (NCHA*T_LEN) + ((size_t)t4 << 2);
    float4 x0 = *(const float4*)(g_xd  + o0);
    float4 x1 = *(const float4*)(g_xd  + o0 + T_LEN);
    float4 l0 = *(const float4*)(g_low + o0);
    float4 l1 = *(const float4*)(g_low + o0 + T_LEN);
    float4 h0 = *(const float4*)(g_high + o0);
    float4 h1 = *(const float4*)(g_high + o0 + T_LEN);
    BSM pl = d_bsm[0*NB + b], pm = d_bsm[1*NB + b], ph = d_bsm[2*NB + b];
    float4 gl, gm, gh;
#define GLANE(L) { \
    float ls = l0.L + l1.L, hs = h0.L + h1.L, xs = x0.L + x1.L; \
    gl.L = comp_gain(fabsf(ls), pl); \
    gm.L = comp_gain(fabsf(xs - ls - hs), pm); \
    gh.L = comp_gain(fabsf(hs), ph); }
    GLANE(x) GLANE(y) GLANE(z) GLANE(w)
#undef GLANE
    size_t gb = (size_t)t4 << 2;
    *(float4*)(g_gin + (size_t)(0*NB + b) * T_LEN + gb) = gl;
    *(float4*)(g_gin + (size_t)(1*NB + b) * T_LEN + gb) = gm;
    *(float4*)(g_gin + (size_t)(2*NB + b) * T_LEN + gb) = gh;
}

// ---------------- nonlinear smoothing (chunked + warmup, contraction-safe) ----------------
template<bool USEMIN>
__device__ __forceinline__ float smstep(float f, float g, float at, float rt)
{
    float d = g - f;
    float u = fmaf(at, d, f);
    float v = fmaf(rt, d, f);
    return USEMIN ? fminf(u, v) : fmaxf(u, v);
}

template<bool USEMIN, bool LIM>
__device__ void smooth_chunk(const float* __restrict__ src, float* __restrict__ dst,
                             float at, float rt, float lt,
                             float f, int wstart, int start, int end)
{
    const int nit = (end - wstart) >> 2;       // always a multiple of 8 here
    const float4* s4 = (const float4*)(src + wstart);
    float4 buf[8];
#pragma unroll
    for (int j = 0; j < 8; ++j) buf[j] = (j < nit) ? __ldg(s4 + j) : make_float4(0.f,0.f,0.f,0.f);
    int t = wstart;
    for (int base = 0; base < nit; base += 8) {
#pragma unroll
        for (int j = 0; j < 8; ++j) {
            float4 v = buf[j];
            int nxt = base + 8 + j;
            if (nxt < nit) buf[j] = __ldg(s4 + nxt);
            float4 r;
            f = smstep<USEMIN>(f, v.x, at, rt); r.x = f;
            f = smstep<USEMIN>(f, v.y, at, rt); r.y = f;
            f = smstep<USEMIN>(f, v.z, at, rt); r.z = f;
            f = smstep<USEMIN>(f, v.w, at, rt); r.w = f;
            if (LIM) {
                r.x = fminf(1.f, lt / fmaxf(r.x, 1e-7f));
                r.y = fminf(1.f, lt / fmaxf(r.y, 1e-7f));
                r.z = fminf(1.f, lt / fmaxf(r.z, 1e-7f));
                r.w = fminf(1.f, lt / fmaxf(r.w, 1e-7f));
            }
            if (t >= start) *(float4*)(dst + t) = r;
            t += 4;
        }
    }
}

__global__ void k_smooth_band()
{
    int tid = blockIdx.x * blockDim.x + threadIdx.x;
    if (tid >= NBS * SM_NCH) return;
    int seq = tid >> 5;          // SM_NCH == 32 -> warp-uniform sequence
    int c   = tid & 31;
    BSM p = d_bsm[seq];
    const float* src = g_gin + (size_t)seq * T_LEN;
    float*       dst = g_gsm + (size_t)seq * T_LEN;
    int start = c * SM_CHUNK, end = start + SM_CHUNK;
    int wstart = start - SM_WARM; if (wstart < 0) wstart = 0;
    float f = (wstart == 0) ? 1.0f : __ldg(src + wstart);
    if (p.useMin) smooth_chunk<true, false>(src, dst, p.at, p.rt, 0.f, f, wstart, start, end);
    else          smooth_chunk<false,false>(src, dst, p.at, p.rt, 0.f, f, wstart, start, end);
}

__global__ void k_smooth_lim()
{
    int tid = blockIdx.x * blockDim.x + threadIdx.x;
    if (tid >= NB * SM_NCH) return;
    int b = tid >> 5;
    int c = tid & 31;
    LSM p = d_lsm[b];
    const float* src = g_det + (size_t)b * T_LEN;
    float*       dst = g_lg  + (size_t)b * T_LEN;
    int start = c * SM_CHUNK, end = start + SM_CHUNK;
    int wstart = start - SM_WARM; if (wstart < 0) wstart = 0;
    float f = (wstart == 0) ? 0.0f : __ldg(src + wstart);
    if (p.useMin) smooth_chunk<true, true>(src, dst, p.at, p.rt, p.lt, f, wstart, start, end);
    else          smooth_chunk<false,true>(src, dst, p.at, p.rt, p.lt, f, wstart, start, end);
}

// ---------------- band mix + limiter detector ----------------
__global__ void k_mix()
{
    int idx = blockIdx.x * blockDim.x + threadIdx.x;
    const int per = T_LEN / 4;
    if (idx >= NB * per) return;
    int b = idx / per, t4 = idx - b * per;
    size_t o0 = (size_t)b * (NCHA*T_LEN) + ((size_t)t4 << 2);
    size_t gb = (size_t)t4 << 2;
    float4 x0 = *(const float4*)(g_xd  + o0);
    float4 x1 = *(const float4*)(g_xd  + o0 + T_LEN);
    float4 l0 = *(const float4*)(g_low + o0);
    float4 l1 = *(const float4*)(g_low + o0 + T_LEN);
    float4 h0 = *(const float4*)(g_high + o0);
    float4 h1 = *(const float4*)(g_high + o0 + T_LEN);
    float4 gl = *(const float4*)(g_gsm + (size_t)(0*NB + b) * T_LEN + gb);
    float4 gm = *(const float4*)(g_gsm + (size_t)(1*NB + b) * T_LEN + gb);
    float4 gh = *(const float4*)(g_gsm + (size_t)(2*NB + b) * T_LEN + gb);
    float mb = d_mb[b], om = 1.f - mb;
    float4 m0, m1, dt;
#define MLANE(L) { \
    float mid0 = x0.L - l0.L - h0.L; \
    float y0 = l0.L*gl.L + mid0*gm.L + h0.L*gh.L; \
    float a0 = mb*y0 + om*x0.L; \
    float mid1 = x1.L - l1.L - h1.L; \
    float y1 = l1.L*gl.L + mid1*gm.L + h1.L*gh.L; \
    float a1 = mb*y1 + om*x1.L; \
    m0.L = a0; m1.L = a1; dt.L = fabsf(a0 + a1); }
    MLANE(x) MLANE(y) MLANE(z) MLANE(w)
#undef MLANE
    *(float4*)(g_xm + o0)         = m0;
    *(float4*)(g_xm + o0 + T_LEN) = m1;
    *(float4*)(g_det + (size_t)b * T_LEN + gb) = dt;
}

// ---------------- final limiter application ----------------
__global__ void k_final(float* __restrict__ out)
{
    int idx = blockIdx.x * blockDim.x + threadIdx.x;
    const int per = T_LEN / 4;
    if (idx >= NB * per) return;
    int b = idx / per, t4 = idx - b * per;
    size_t o0 = (size_t)b * (NCHA*T_LEN) + ((size_t)t4 << 2);
    float4 lg = *(const float4*)(g_lg + (size_t)b * T_LEN + ((size_t)t4 << 2));
    float4 m0 = *(const float4*)(g_xm + o0);
    float4 m1 = *(const float4*)(g_xm + o0 + T_LEN);
    m0.x *= lg.x; m0.y *= lg.y; m0.z *= lg.z; m0.w *= lg.w;
    m1.x *= lg.x; m1.y *= lg.y; m1.z *= lg.z; m1.w *= lg.w;
    *(float4*)(out + o0)         = m0;
    *(float4*)(out + o0 + T_LEN) = m1;
}

// ---------------- launcher ----------------
extern "C" void kernel_launch(void* const* d_in, const int* in_sizes, int n_in,
                              void* d_out, int out_size)
{
    const float* x     = (const float*)d_in[0];
    const float* drive = (const float*)d_in[1];
    const float* dmix  = (const float*)d_in[2];
    const float* locut = (const float*)d_in[3];
    const float* hicut = (const float*)d_in[4];
    const float* mbmix = (const float*)d_in[5];
    const float* ct    = (const float*)d_in[6];
    const float* cr    = (const float*)d_in[7];
    const float* et    = (const float*)d_in[8];
    const float* er    = (const float*)d_in[9];
    const float* atms  = (const float*)d_in[10];
    const float* rtms  = (const float*)d_in[11];
    const float* lth   = (const float*)d_in[12];
    const float* lat   = (const float*)d_in[13];
    const float* lrt   = (const float*)d_in[14];
    (void)in_sizes; (void)n_in; (void)out_size;

    k_setup<<<1, 64>>>(drive, dmix, locut, hicut, mbmix, ct, cr, et, er,
                       atms, rtms, lth, lat, lrt);
    k_dist<<<(NSEQ*T_LEN/4 + 255)/256, 256>>>(x);
    k_biquad<<<64, BQ_NT>>>(0);
    k_biquad<<<64, BQ_NT>>>(1);
    k_bandgain<<<(NB*T_LEN/4 + 255)/256, 256>>>();
    k_smooth_band<<<(NBS*SM_NCH + 127)/128, 128>>>();
    k_mix<<<(NB*T_LEN/4 + 255)/256, 256>>>();
    k_smooth_lim<<<(NB*SM_NCH + 127)/128, 128>>>();
    k_final<<<(NB*T_LEN/4 + 255)/256, 256>>>((float*)d_out);
}